// round 13
// baseline (speedup 1.0000x reference)
#include <cuda_runtime.h>
#include <cstdint>

// BERT_CRF: B=64, S=512, H=768, L=9 — single kernel, 256-thread blocks.
//   grid 512 = 64 batches x 8 chunks of 64 timesteps.
//   GEMM: 8 warps, k-subslice 4/warp, R=2 rows/lane, cp.async double-buffer,
//         W broadcast from smem.
//   Scan: two parallel 32-step half-products (warps 0-2 / 4-6, named bars),
//         warp 3 numerator, then 9x9 log-semiring compose.
//   Tail: per-batch ticket -> warp-0 finalize; global ticket -> 64->1 sum.

#define BB 64
#define SS 512
#define HH 768
#define LL 9
#define NC 8        // chunks per batch
#define CL 64       // timesteps per chunk
#define HCL 32      // half chunk
#define NST2 81
#define KC 32       // k-chunk width
#define NKC 24      // 768/32
#define SHS 36      // sH row stride: conflict-free LDS.128

#define LOG2E 1.4426950408889634f
#define LN2   0.6931471805599453f

__device__ float g_em0[BB * LL];
__device__ float g_P[BB * NC * NST2];
__device__ float g_numpart[BB * NC];
__device__ float g_partial[BB];
__device__ unsigned g_bt[BB];     // per-batch tickets
__device__ unsigned g_tick;       // global ticket

__device__ __forceinline__ float ex2f_(float x) {
    float y; asm("ex2.approx.ftz.f32 %0, %1;" : "=f"(y) : "f"(x)); return y;
}
__device__ __forceinline__ float lg2f_(float x) {
    float y; asm("lg2.approx.ftz.f32 %0, %1;" : "=f"(y) : "f"(x)); return y;
}
__device__ __forceinline__ void cp16(void* dst, const void* src) {
    uint32_t d = (uint32_t)__cvta_generic_to_shared(dst);
    asm volatile("cp.async.cg.shared.global [%0], [%1], 16;" :: "r"(d), "l"(src));
}
__device__ __forceinline__ void cp_commit() {
    asm volatile("cp.async.commit_group;");
}
template <int N> __device__ __forceinline__ void cp_wait() {
    asm volatile("cp.async.wait_group %0;" :: "n"(N));
}

// ---------------------------------------------------------------------------
__global__ __launch_bounds__(256) void fused_kernel(
    const float* __restrict__ hidden,   // [B*S, H]
    const int*   __restrict__ mask,     // [B,S]
    const int*   __restrict__ labels,   // [B,S]
    const float* __restrict__ Wm,       // [H, L]
    const float* __restrict__ bias,     // [L]
    const float* __restrict__ trans,    // [L,L]
    const float* __restrict__ start_t,  // [L]
    const float* __restrict__ end_t,    // [L]
    float*       __restrict__ out)      // [1]
{
    __shared__ float sW[HH * LL];          // 27648 B
    __shared__ float sH[2][CL * SHS];      // 2 x 9216 B
    __shared__ float sEm[CL * LL];         // 2304 B
    __shared__ float sT[NST2];
    __shared__ float sPA[2][NST2];
    __shared__ float sPB[2][NST2];
    __shared__ float sAfin[NST2];
    __shared__ float sBfin[NST2];
    __shared__ int   sMask[CL];
    __shared__ unsigned s_tk;

    float* sRed = &sH[0][0];   // 8*64*9 = 4608 floats = both sH buffers (post-GEMM)

    const int tid = threadIdx.x;
    const int b = blockIdx.x >> 3;
    const int c = blockIdx.x & 7;
    const size_t row0 = (size_t)b * SS + c * CL;

    // staging: 4 threads per row, 2 float4 each
    const int srow = tid >> 2;
    const int sc   = tid & 3;
    const float* gsrc = hidden + (row0 + srow) * HH + sc * 4;

#pragma unroll
    for (int i = 0; i < 2; ++i)
        cp16(&sH[0][srow * SHS + sc * 4 + i * 16], gsrc + i * 16);
    cp_commit();

    // stage W + small tables (overlaps with cp.async)
    {
        const float4* W4 = (const float4*)Wm;
        for (int i = tid; i < (HH * LL) / 4; i += 256)
            ((float4*)sW)[i] = W4[i];
    }
    if (tid < NST2) sT[tid] = trans[tid];
    if (tid < CL)   sMask[tid] = mask[b * SS + c * CL + tid];

    const int w = tid >> 5;    // warp: k-subslice [4w, 4w+4) of each chunk
    const int r = tid & 31;    // lane: rows r and r+32

    float acc0[LL], acc1[LL];
#pragma unroll
    for (int l = 0; l < LL; ++l) { acc0[l] = 0.f; acc1[l] = 0.f; }

    for (int kc = 0; kc < NKC; ++kc) {
        if (kc + 1 < NKC) {
            const float* gn = gsrc + (kc + 1) * KC;
            float* dst = &sH[(kc + 1) & 1][srow * SHS + sc * 4];
#pragma unroll
            for (int i = 0; i < 2; ++i)
                cp16(dst + i * 16, gn + i * 16);
            cp_commit();
            cp_wait<1>();
        } else {
            cp_wait<0>();
        }
        __syncthreads();

        const float* hb = &sH[kc & 1][0];
        const int kl = w * 4;
        float4 h0 = *(const float4*)&hb[r * SHS + kl];
        float4 h1 = *(const float4*)&hb[(r + 32) * SHS + kl];
        const int k0 = kc * KC + kl;
        float wreg[36];
#pragma unroll
        for (int q = 0; q < 9; ++q)
            *(float4*)&wreg[q * 4] = ((const float4*)&sW[k0 * LL])[q];
#pragma unroll
        for (int s = 0; s < 4; ++s) {
            float hv0 = (s == 0) ? h0.x : (s == 1) ? h0.y : (s == 2) ? h0.z : h0.w;
            float hv1 = (s == 0) ? h1.x : (s == 1) ? h1.y : (s == 2) ? h1.z : h1.w;
#pragma unroll
            for (int l = 0; l < LL; ++l) {
                acc0[l] = fmaf(hv0, wreg[s * LL + l], acc0[l]);
                acc1[l] = fmaf(hv1, wreg[s * LL + l], acc1[l]);
            }
        }
        __syncthreads();
    }

    // ---- reduce 8 k-subslice partials per row (sRed spans both sH bufs) ----
#pragma unroll
    for (int l = 0; l < LL; ++l) {
        sRed[(w * CL + r) * LL + l]      = acc0[l];
        sRed[(w * CL + r + 32) * LL + l] = acc1[l];
    }
    __syncthreads();

    if (tid < CL) {
#pragma unroll
        for (int l = 0; l < LL; ++l) {
            float em = bias[l];
#pragma unroll
            for (int s = 0; s < 8; ++s)
                em += sRed[(s * CL + tid) * LL + l];
            sEm[tid * LL + l] = em;
        }
        if (c == 0 && tid == 0) {
#pragma unroll
            for (int l = 0; l < LL; ++l) g_em0[b * LL + l] = sEm[l];
        }
    }
    // identity init for both half-product matrices
    if (tid >= 128 && tid < 224) {            // warps 4-6 init both (96 threads)
        int lane = tid & 31;
        int e = ((tid >> 5) - 4) * 27 + lane;
        if (lane < 27) {
            int i = e / LL, j = e - i * LL;
            float idv = (i == j) ? 0.f : -1e30f;
            sPA[0][e] = idv;
            sPB[0][e] = idv;
        }
    }
    __syncthreads();

    if (tid >= 96 && tid < 128) {
        // ---- warp 3: numerator partial (2 timesteps per lane) ----
        const int l = tid - 96;
        float v = 0.f;
        {
            const int t = c * CL + l;
            if (t >= 1 && sMask[l]) {
                int lt  = labels[b * SS + t];
                int ltp = labels[b * SS + t - 1];
                v += sT[ltp * LL + lt] + sEm[l * LL + lt];
            }
        }
        {
            const int t = c * CL + l + 32;
            if (sMask[l + 32]) {
                int lt  = labels[b * SS + t];
                int ltp = labels[b * SS + t - 1];
                v += sT[ltp * LL + lt] + sEm[(l + 32) * LL + lt];
            }
        }
#pragma unroll
        for (int o = 16; o > 0; o >>= 1) v += __shfl_xor_sync(0xffffffffu, v, o);
        if (l == 0) g_numpart[b * NC + c] = v;
    } else if (tid < 96 || (tid >= 128 && tid < 224)) {
        // ---- half-product scan: A = warps 0-2 (bar 1), B = warps 4-6 (bar 2)
        const bool isA = (tid < 96);
        const int lane = tid & 31;
        const int wg   = isA ? (tid >> 5) : ((tid >> 5) - 4);
        const int e = wg * 27 + lane;
        const bool act = (lane < 27);
        const int i = e / LL;
        const int j = e - i * LL;
        float (*sP)[NST2] = isA ? sPA : sPB;
        float* sFin = isA ? sAfin : sBfin;
        const int barid = isA ? 1 : 2;

        float Tcol[LL];
        if (act) {
#pragma unroll
            for (int k = 0; k < LL; ++k) Tcol[k] = sT[k * LL + j] * LOG2E;
        }

        int cur = 0;
        const int base = c * CL + (isA ? 0 : HCL);
        const int t0 = (isA && c == 0) ? base + 1 : base;
        const int t1 = base + HCL;
        for (int t = t0; t < t1; ++t) {
            if (!sMask[t - c * CL]) continue;    // uniform within the 96-group
            if (act) {
                const float* Pr = &sP[cur][i * LL];
                float x[LL];
                float mx = -1e30f;
#pragma unroll
                for (int k = 0; k < LL; ++k) {
                    x[k] = Pr[k] + Tcol[k];
                    mx = fmaxf(mx, x[k]);
                }
                float s = 0.f;
#pragma unroll
                for (int k = 0; k < LL; ++k) s += ex2f_(x[k] - mx);
                sP[cur ^ 1][e] = fmaf(sEm[(t - c * CL) * LL + j], LOG2E,
                                      mx + lg2f_(s));
            }
            asm volatile("bar.sync %0, 96;" :: "r"(barid) : "memory");
            cur ^= 1;
        }
        if (act) sFin[e] = sP[cur][e];   // own entry: no extra sync needed
    }
    __syncthreads();

    // ---- compose: full = A o B (base-2 log semiring), warps 0-2 ----
    if (tid < 96) {
        const int lane = tid & 31;
        const int e = (tid >> 5) * 27 + lane;
        if (lane < 27) {
            const int i = e / LL;
            const int j = e - i * LL;
            float x[LL];
            float mx = -1e30f;
#pragma unroll
            for (int k = 0; k < LL; ++k) {
                x[k] = sAfin[i * LL + k] + sBfin[k * LL + j];
                mx = fmaxf(mx, x[k]);
            }
            float s = 0.f;
#pragma unroll
            for (int k = 0; k < LL; ++k) s += ex2f_(x[k] - mx);
            g_P[((size_t)b * NC + c) * NST2 + e] = mx + lg2f_(s);
        }
    }

    // ================= tail: per-batch ticket + finalize =================
    __threadfence();
    __syncthreads();
    if (tid == 0) s_tk = atomicAdd(&g_bt[b], 1u);
    __syncthreads();
    if (s_tk != NC - 1) return;

    if (tid >= 32) return;
    const int lane = tid;
    __threadfence();

    float* sPm = &sH[0][0];            // 648 floats, free now
    for (int idx = lane; idx < NC * NST2; idx += 32)
        sPm[idx] = g_P[(size_t)b * NC * NST2 + idx];

    int ms = 0;
    for (int t = lane; t < SS; t += 32) ms += mask[b * SS + t];
#pragma unroll
    for (int o = 16; o > 0; o >>= 1) ms += __shfl_xor_sync(0xffffffffu, ms, o);

    float np = (lane < NC) ? g_numpart[b * NC + lane] : 0.f;
#pragma unroll
    for (int o = 16; o > 0; o >>= 1) np += __shfl_xor_sync(0xffffffffu, np, o);

    __syncwarp();

    const int jj = (lane < LL) ? lane : 0;
    float a[LL];
#pragma unroll
    for (int q = 0; q < LL; ++q)
        a[q] = LOG2E * (start_t[q] + g_em0[b * LL + q]);

    for (int cc = 0; cc < NC; ++cc) {
        float x[LL];
        float mx = -1e30f;
#pragma unroll
        for (int q = 0; q < LL; ++q) {
            x[q] = a[q] + sPm[cc * NST2 + q * LL + jj];
            mx = fmaxf(mx, x[q]);
        }
        float s = 0.f;
#pragma unroll
        for (int q = 0; q < LL; ++q) s += ex2f_(x[q] - mx);
        float pn = mx + lg2f_(s);
#pragma unroll
        for (int q = 0; q < LL; ++q) a[q] = __shfl_sync(0xffffffffu, pn, q);
    }

    float x[LL];
    float mx = -1e30f;
#pragma unroll
    for (int q = 0; q < LL; ++q) {
        x[q] = fmaf(end_t[q], LOG2E, a[q]);
        mx = fmaxf(mx, x[q]);
    }
    float s = 0.f;
#pragma unroll
    for (int q = 0; q < LL; ++q) s += ex2f_(x[q] - mx);
    float denom = LN2 * (mx + lg2f_(s));

    if (lane == 0) {
        int last = ms - 1;
        int lab0 = labels[b * SS];
        int labL = labels[b * SS + last];
        float num = start_t[lab0] + g_em0[b * LL + lab0] + np + end_t[labL];
        g_partial[b] = denom - num;
        g_bt[b] = 0;               // reset per-batch ticket for graph replay
    }
    __threadfence();

    unsigned gt = 0;
    if (lane == 0) gt = atomicAdd(&g_tick, 1u);
    gt = __shfl_sync(0xffffffffu, gt, 0);
    if (gt == BB - 1) {
        float v = g_partial[lane] + g_partial[lane + 32];
#pragma unroll
        for (int o = 16; o > 0; o >>= 1) v += __shfl_xor_sync(0xffffffffu, v, o);
        if (lane == 0) {
            out[0] = v;
            g_tick = 0;            // reset global ticket for graph replay
        }
    }
}

// ---------------------------------------------------------------------------
extern "C" void kernel_launch(void* const* d_in, const int* in_sizes, int n_in,
                              void* d_out, int out_size)
{
    (void)in_sizes; (void)n_in; (void)out_size;
    const float* hidden  = (const float*)d_in[0];
    const int*   mask    = (const int*)  d_in[1];
    const int*   labels  = (const int*)  d_in[2];
    const float* Wm      = (const float*)d_in[3];
    const float* bias    = (const float*)d_in[4];
    const float* start_t = (const float*)d_in[5];
    const float* end_t   = (const float*)d_in[6];
    const float* trans   = (const float*)d_in[7];

    fused_kernel<<<BB * NC, 256>>>(hidden, mask, labels, Wm, bias, trans,
                                   start_t, end_t, (float*)d_out);
}

// round 15
// speedup vs baseline: 1.1449x; 1.1449x over previous
#include <cuda_runtime.h>
#include <cstdint>

// BERT_CRF: B=64, S=512, H=768, L=9 — single kernel, 128-thread blocks.
//   grid 512 = 64 batches x 8 chunks of 64 timesteps.
//   GEMM: W via warp-uniform __ldg (L1/L2-hot, no smem), H cp.async
//         double-buffered KC=64 chunks, R=2 rows/lane, 4 warps.
//   Scan: 63-step 9x9 log-semiring chunk product (warps 0-2) + numerator.
//   Tail: per-batch ticket -> warp-0 finalize; global ticket -> 64->1 sum.

#define BB 64
#define SS 512
#define HH 768
#define LL 9
#define NC 8        // chunks per batch
#define CL 64       // timesteps per chunk
#define NST2 81
#define KC 64       // k-chunk width
#define NKC 12      // 768/64
#define SHS 68      // sH row stride: 68 mod 32 = 4 -> conflict-free LDS.128

#define LOG2E 1.4426950408889634f
#define LN2   0.6931471805599453f

__device__ float g_em0[BB * LL];
__device__ float g_P[BB * NC * NST2];
__device__ float g_numpart[BB * NC];
__device__ float g_partial[BB];
__device__ unsigned g_bt[BB];     // per-batch tickets
__device__ unsigned g_tick;       // global ticket

__device__ __forceinline__ float ex2f_(float x) {
    float y; asm("ex2.approx.ftz.f32 %0, %1;" : "=f"(y) : "f"(x)); return y;
}
__device__ __forceinline__ float lg2f_(float x) {
    float y; asm("lg2.approx.ftz.f32 %0, %1;" : "=f"(y) : "f"(x)); return y;
}
__device__ __forceinline__ void cp16(void* dst, const void* src) {
    uint32_t d = (uint32_t)__cvta_generic_to_shared(dst);
    asm volatile("cp.async.cg.shared.global [%0], [%1], 16;" :: "r"(d), "l"(src));
}
__device__ __forceinline__ void cp_commit() {
    asm volatile("cp.async.commit_group;");
}
template <int N> __device__ __forceinline__ void cp_wait() {
    asm volatile("cp.async.wait_group %0;" :: "n"(N));
}

// ---------------------------------------------------------------------------
// static smem: sH 34816 + sT 324 + sP 648 + sMask 256 + s_tk 4 ~= 36.1 KB
// ---------------------------------------------------------------------------
__global__ __launch_bounds__(128) void fused_kernel(
    const float* __restrict__ hidden,   // [B*S, H]
    const int*   __restrict__ mask,     // [B,S]
    const int*   __restrict__ labels,   // [B,S]
    const float* __restrict__ Wm,       // [H, L]
    const float* __restrict__ bias,     // [L]
    const float* __restrict__ trans,    // [L,L]
    const float* __restrict__ start_t,  // [L]
    const float* __restrict__ end_t,    // [L]
    float*       __restrict__ out)      // [1]
{
    __shared__ float sH[2][CL * SHS];      // 2 x 17408 B
    __shared__ float sT[NST2];
    __shared__ float sP[2][NST2];
    __shared__ int   sMask[CL];
    __shared__ unsigned s_tk;

    // aliases valid after the GEMM mainloop (guarded by __syncthreads):
    float* sRed = &sH[0][0];               // 4*64*9 = 2304 floats, fits sH[0]
    float* sEm  = &sH[1][0];               // 64*9   = 576 floats into sH[1]

    const int tid = threadIdx.x;
    const int b = blockIdx.x >> 3;
    const int c = blockIdx.x & 7;
    const size_t row0 = (size_t)b * SS + c * CL;

    // staging map: 2 threads per row, 32 floats (8 x float4) each
    const int srow = tid >> 1;
    const int sc   = tid & 1;
    const float* gsrc = hidden + (row0 + srow) * HH + sc * 32;

    // prologue: async-load k-chunk 0 into sH[0]
#pragma unroll
    for (int i = 0; i < 8; ++i)
        cp16(&sH[0][srow * SHS + sc * 32 + i * 4], gsrc + i * 4);
    cp_commit();

    if (tid < NST2) sT[tid] = trans[tid];
    if (tid < CL)   sMask[tid] = mask[b * SS + c * CL + tid];

    const int w = tid >> 5;                // warp: k-subslice [16w, 16w+16) per chunk
    const int r = tid & 31;                // lane: rows r and r+32

    float acc0[LL], acc1[LL];
#pragma unroll
    for (int l = 0; l < LL; ++l) { acc0[l] = 0.f; acc1[l] = 0.f; }

    for (int kc = 0; kc < NKC; ++kc) {
        if (kc + 1 < NKC) {
            const float* gn = gsrc + (kc + 1) * KC;
            float* dst = &sH[(kc + 1) & 1][srow * SHS + sc * 32];
#pragma unroll
            for (int i = 0; i < 8; ++i)
                cp16(dst + i * 4, gn + i * 4);
            cp_commit();
            cp_wait<1>();                  // chunk kc resident
        } else {
            cp_wait<0>();
        }
        __syncthreads();

        const float* hb = &sH[kc & 1][0];
#pragma unroll
        for (int g = 0; g < 4; ++g) {
            const int kl = w * 16 + g * 4;
            float4 h0 = *(const float4*)&hb[r * SHS + kl];
            float4 h1 = *(const float4*)&hb[(r + 32) * SHS + kl];
            const int k0 = kc * KC + kl;   // multiple of 4
            // warp-uniform W block [k0..k0+3][0..8]: 9 aligned float4 via L1/L2
            const float4* W4 = (const float4*)(Wm + k0 * LL);
            float wreg[36];
#pragma unroll
            for (int q = 0; q < 9; ++q)
                *(float4*)&wreg[q * 4] = __ldg(&W4[q]);
#pragma unroll
            for (int s = 0; s < 4; ++s) {
                float hv0 = (s == 0) ? h0.x : (s == 1) ? h0.y : (s == 2) ? h0.z : h0.w;
                float hv1 = (s == 0) ? h1.x : (s == 1) ? h1.y : (s == 2) ? h1.z : h1.w;
#pragma unroll
                for (int l = 0; l < LL; ++l) {
                    acc0[l] = fmaf(hv0, wreg[s * LL + l], acc0[l]);
                    acc1[l] = fmaf(hv1, wreg[s * LL + l], acc1[l]);
                }
            }
        }
        __syncthreads();                   // buffer consumed before reuse
    }

    // ---- reduction across the 4 k-subslice warps (sRed = sH[0]) ----
#pragma unroll
    for (int l = 0; l < LL; ++l) {
        sRed[(w * CL + r) * LL + l]        = acc0[l];
        sRed[(w * CL + r + 32) * LL + l]   = acc1[l];
    }
    __syncthreads();

    if (tid < CL) {
#pragma unroll
        for (int l = 0; l < LL; ++l) {
            float em = bias[l];
#pragma unroll
            for (int s = 0; s < 4; ++s)
                em += sRed[(s * CL + tid) * LL + l];
            sEm[tid * LL + l] = em;         // sEm = sH[1], disjoint from sRed
        }
        if (c == 0 && tid == 0) {
#pragma unroll
            for (int l = 0; l < LL; ++l) g_em0[b * LL + l] = sEm[l];
        }
    }
    if (tid < 96) {
        int lane = tid & 31;
        int e = (tid >> 5) * 27 + lane;
        if (lane < 27) {
            int i = e / LL, j = e - i * LL;
            sP[0][e] = (i == j) ? 0.f : -1e30f;
        }
    }
    __syncthreads();

    if (tid >= 96) {
        // ---- warp 3: numerator partial (2 timesteps per lane) ----
        const int l = tid - 96;
        float v = 0.f;
        {
            const int t = c * CL + l;
            if (t >= 1 && sMask[l]) {
                int lt  = labels[b * SS + t];
                int ltp = labels[b * SS + t - 1];
                v += sT[ltp * LL + lt] + sEm[l * LL + lt];
            }
        }
        {
            const int t = c * CL + l + 32;     // always >= 32 >= 1
            if (sMask[l + 32]) {
                int lt  = labels[b * SS + t];
                int ltp = labels[b * SS + t - 1];
                v += sT[ltp * LL + lt] + sEm[(l + 32) * LL + lt];
            }
        }
#pragma unroll
        for (int o = 16; o > 0; o >>= 1) v += __shfl_xor_sync(0xffffffffu, v, o);
        if (l == 0) g_numpart[b * NC + c] = v;
    } else {
        // ---- warps 0-2: log-semiring chunk-matrix scan (base-2) ----
        const int lane = tid & 31;
        const int e = (tid >> 5) * 27 + lane;
        const bool act = (lane < 27);
        const int i = e / LL;
        const int j = e - i * LL;

        float Tcol[LL];
        if (act) {
#pragma unroll
            for (int k = 0; k < LL; ++k) Tcol[k] = sT[k * LL + j] * LOG2E;
        }

        int cur = 0;
        const int t0 = (c == 0) ? 1 : c * CL;
        const int t1 = c * CL + CL;
        for (int t = t0; t < t1; ++t) {
            if (!sMask[t - c * CL]) continue;    // block-uniform
            if (act) {
                const float* Pr = &sP[cur][i * LL];
                float x[LL];
                float mx = -1e30f;
#pragma unroll
                for (int k = 0; k < LL; ++k) {
                    x[k] = Pr[k] + Tcol[k];
                    mx = fmaxf(mx, x[k]);
                }
                float s = 0.f;
#pragma unroll
                for (int k = 0; k < LL; ++k) s += ex2f_(x[k] - mx);
                sP[cur ^ 1][e] = fmaf(sEm[(t - c * CL) * LL + j], LOG2E,
                                      mx + lg2f_(s));
            }
            asm volatile("bar.sync 1, 96;" ::: "memory");
            cur ^= 1;
        }
        if (act) g_P[((size_t)b * NC + c) * NST2 + e] = sP[cur][e];
    }

    // ================= tail: per-batch ticket + finalize =================
    __threadfence();
    __syncthreads();
    if (tid == 0) s_tk = atomicAdd(&g_bt[b], 1u);
    __syncthreads();
    if (s_tk != NC - 1) return;

    if (tid >= 32) return;
    const int lane = tid;
    __threadfence();

    float* sPm = &sH[0][0];            // 648 floats, free now
    for (int idx = lane; idx < NC * NST2; idx += 32)
        sPm[idx] = g_P[(size_t)b * NC * NST2 + idx];

    int ms = 0;
    for (int t = lane; t < SS; t += 32) ms += mask[b * SS + t];
#pragma unroll
    for (int o = 16; o > 0; o >>= 1) ms += __shfl_xor_sync(0xffffffffu, ms, o);

    float np = (lane < NC) ? g_numpart[b * NC + lane] : 0.f;
#pragma unroll
    for (int o = 16; o > 0; o >>= 1) np += __shfl_xor_sync(0xffffffffu, np, o);

    __syncwarp();

    const int jj = (lane < LL) ? lane : 0;
    float a[LL];
#pragma unroll
    for (int q = 0; q < LL; ++q)
        a[q] = LOG2E * (start_t[q] + g_em0[b * LL + q]);

    for (int cc = 0; cc < NC; ++cc) {
        float x[LL];
        float mx = -1e30f;
#pragma unroll
        for (int q = 0; q < LL; ++q) {
            x[q] = a[q] + sPm[cc * NST2 + q * LL + jj];
            mx = fmaxf(mx, x[q]);
        }
        float s = 0.f;
#pragma unroll
        for (int q = 0; q < LL; ++q) s += ex2f_(x[q] - mx);
        float pn = mx + lg2f_(s);
#pragma unroll
        for (int q = 0; q < LL; ++q) a[q] = __shfl_sync(0xffffffffu, pn, q);
    }

    float x[LL];
    float mx = -1e30f;
#pragma unroll
    for (int q = 0; q < LL; ++q) {
        x[q] = fmaf(end_t[q], LOG2E, a[q]);
        mx = fmaxf(mx, x[q]);
    }
    float s = 0.f;
#pragma unroll
    for (int q = 0; q < LL; ++q) s += ex2f_(x[q] - mx);
    float denom = LN2 * (mx + lg2f_(s));

    if (lane == 0) {
        int last = ms - 1;
        int lab0 = labels[b * SS];
        int labL = labels[b * SS + last];
        float num = start_t[lab0] + g_em0[b * LL + lab0] + np + end_t[labL];
        g_partial[b] = denom - num;
        g_bt[b] = 0;               // reset per-batch ticket for graph replay
    }
    __threadfence();

    unsigned gt = 0;
    if (lane == 0) gt = atomicAdd(&g_tick, 1u);
    gt = __shfl_sync(0xffffffffu, gt, 0);
    if (gt == BB - 1) {
        float v = g_partial[lane] + g_partial[lane + 32];
#pragma unroll
        for (int o = 16; o > 0; o >>= 1) v += __shfl_xor_sync(0xffffffffu, v, o);
        if (lane == 0) {
            out[0] = v;
            g_tick = 0;            // reset global ticket for graph replay
        }
    }
}

// ---------------------------------------------------------------------------
extern "C" void kernel_launch(void* const* d_in, const int* in_sizes, int n_in,
                              void* d_out, int out_size)
{
    (void)in_sizes; (void)n_in; (void)out_size;
    const float* hidden  = (const float*)d_in[0];
    const int*   mask    = (const int*)  d_in[1];
    const int*   labels  = (const int*)  d_in[2];
    const float* Wm      = (const float*)d_in[3];
    const float* bias    = (const float*)d_in[4];
    const float* start_t = (const float*)d_in[5];
    const float* end_t   = (const float*)d_in[6];
    const float* trans   = (const float*)d_in[7];

    fused_kernel<<<BB * NC, 128>>>(hidden, mask, labels, Wm, bias, trans,
                                   start_t, end_t, (float*)d_out);
}